// round 8
// baseline (speedup 1.0000x reference)
#include <cuda_runtime.h>
#include <cuda_bf16.h>
#include <math.h>
#include <stdint.h>

// ---------------- problem constants ----------------
#define BATCH   2
#define SEQL    2048
#define DMODEL  1024
#define DSTATE  16
#define DINNER  2048
#define NROWS   (BATCH * SEQL)   // 4096

// ---------------- scratch (static device globals; no allocation) ----------------
__device__ float g_xz[NROWS * 2 * DINNER];     // (xa | z)
__device__ float g_xc[NROWS * DINNER];         // conv+silu
__device__ float g_bct[32 * NROWS];            // BC TRANSPOSED: [c][row]
__device__ float g_gg[NROWS * DINNER];         // scan output, tf32, K-PERMUTED
__device__ float g_xr[NROWS * DMODEL];         // x, tf32, K-PERMUTED
__device__ float g_wt_in[2 * DINNER * DMODEL]; // W_in^T [4096][1024], tf32, K-perm
__device__ float g_wt_out[DMODEL * DINNER];    // W_out^T [1024][2048], tf32, K-perm

// ---------------- helpers ----------------
__device__ __forceinline__ void cpasync16(void* dst, const void* src) {
    uint32_t d = (uint32_t)__cvta_generic_to_shared(dst);
    asm volatile("cp.async.cg.shared.global [%0], [%1], 16;\n" :: "r"(d), "l"(src));
}
#define CP_COMMIT() asm volatile("cp.async.commit_group;\n" ::: "memory")
#define CP_WAIT0()  asm volatile("cp.async.wait_group 0;\n" ::: "memory")

__device__ __forceinline__ float round_tf32(float x) {
    uint32_t r;
    asm("cvt.rna.tf32.f32 %0, %1;" : "=r"(r) : "f"(x));
    return __uint_as_float(r);
}
// position of original k inside the permuted 8-group: 0,4,1,5,2,6,3,7
__device__ __forceinline__ int kperm_pos(int k) {
    return (k & ~7) | ((k & 4) ? (((k & 3) << 1) | 1) : ((k & 3) << 1));
}

// =======================================================================
// TF32 mma.sync GEMM, K-PERMUTED operands, B pre-transposed to [N,K].
// C[M,N] = A[M,K] @ B^T.  CTA tile TM x 128 x 16, 128 thr = 4 warps (2x2).
// Fragment loads are LDS.64. Pipeline: wait -> sync -> issue-next -> compute
// (race-free: stage for chunk kt+1 was last read in iteration kt-1, and the
// sync at iteration kt orders all warps past that compute).
// =======================================================================
#define SSTR 24

template<int TM>
__global__ __launch_bounds__(128)
void tf32gemm_kernel(const float* __restrict__ A, const float* __restrict__ Bt,
                     float* __restrict__ C, int M, int N, int K)
{
    constexpr int WM = TM / 2;     // warp m extent
    constexpr int MT = TM / 32;    // m16 tiles per warp

    __shared__ float As[2][TM][SSTR];
    __shared__ float Bs[2][128][SSTR];

    const int tid  = threadIdx.x;
    const int warp = tid >> 5;
    const int lane = tid & 31;
    const int wm   = warp >> 1;
    const int wn   = warp & 1;
    const int g    = lane >> 2;
    const int t    = lane & 3;

    const int m0 = blockIdx.y * TM;
    const int n0 = blockIdx.x * 128;

    float acc[MT][8][4];
    #pragma unroll
    for (int i = 0; i < MT; i++)
        #pragma unroll
        for (int j = 0; j < 8; j++)
            #pragma unroll
            for (int v = 0; v < 4; v++) acc[i][j][v] = 0.f;

    #define LOAD_CHUNK(kt, st) do {                                            \
        _Pragma("unroll")                                                      \
        for (int it = 0; it < TM / 32; it++) {                                 \
            int id = it * 128 + tid;                                           \
            int row = id >> 2, seg = (id & 3) * 4;                             \
            cpasync16(&As[st][row][seg],                                       \
                      A + (size_t)(m0 + row) * K + (kt) * 16 + seg);           \
        }                                                                      \
        _Pragma("unroll")                                                      \
        for (int it = 0; it < 4; it++) {                                       \
            int id = it * 128 + tid;                                           \
            int row = id >> 2, seg = (id & 3) * 4;                             \
            cpasync16(&Bs[st][row][seg],                                       \
                      Bt + (size_t)(n0 + row) * K + (kt) * 16 + seg);          \
        }                                                                      \
        CP_COMMIT();                                                           \
    } while (0)

    const int nk = K / 16;

    LOAD_CHUNK(0, 0);

    for (int kt = 0; kt < nk; kt++) {
        const int cur = kt & 1;
        CP_WAIT0();              // chunk kt landed
        __syncthreads();         // all warps past compute of kt-1 (stage cur^1)
        if (kt + 1 < nk)
            LOAD_CHUNK(kt + 1, cur ^ 1);   // overlaps compute below

        #pragma unroll
        for (int kk = 0; kk < 16; kk += 8) {
            float2 av0[MT], av1[MT], bv[8];
            #pragma unroll
            for (int mt = 0; mt < MT; mt++) {
                const int mr = wm * WM + mt * 16 + g;
                av0[mt] = *(const float2*)&As[cur][mr][kk + 2 * t];
                av1[mt] = *(const float2*)&As[cur][mr + 8][kk + 2 * t];
            }
            #pragma unroll
            for (int nt = 0; nt < 8; nt++) {
                const int nr = wn * 64 + nt * 8 + g;
                bv[nt] = *(const float2*)&Bs[cur][nr][kk + 2 * t];
            }
            #pragma unroll
            for (int mt = 0; mt < MT; mt++)
                #pragma unroll
                for (int nt = 0; nt < 8; nt++) {
                    float* c = acc[mt][nt];
                    asm volatile(
                        "mma.sync.aligned.m16n8k8.row.col.f32.tf32.tf32.f32 "
                        "{%0,%1,%2,%3}, {%4,%5,%6,%7}, {%8,%9}, {%0,%1,%2,%3};\n"
                        : "+f"(c[0]), "+f"(c[1]), "+f"(c[2]), "+f"(c[3])
                        : "r"(__float_as_uint(av0[mt].x)), "r"(__float_as_uint(av1[mt].x)),
                          "r"(__float_as_uint(av0[mt].y)), "r"(__float_as_uint(av1[mt].y)),
                          "r"(__float_as_uint(bv[nt].x)),  "r"(__float_as_uint(bv[nt].y)));
                }
        }
    }
    #undef LOAD_CHUNK

    #pragma unroll
    for (int mt = 0; mt < MT; mt++) {
        #pragma unroll
        for (int nt = 0; nt < 8; nt++) {
            const size_t row = (size_t)m0 + wm * WM + mt * 16 + g;
            const int    col = n0 + wn * 64 + nt * 8 + 2 * t;
            *(float2*)(C + row * N + col)       = make_float2(acc[mt][nt][0], acc[mt][nt][1]);
            *(float2*)(C + (row + 8) * N + col) = make_float2(acc[mt][nt][2], acc[mt][nt][3]);
        }
    }
}

// ---------------- round + K-permute (linear, rows are multiples of 8) ----------
__global__ void round_perm_kernel(const float* __restrict__ in,
                                  float* __restrict__ out, int n8)
{
    int i = blockIdx.x * blockDim.x + threadIdx.x;
    if (i >= n8) return;
    float4 v0 = ((const float4*)in)[2 * i];
    float4 v1 = ((const float4*)in)[2 * i + 1];
    float4 o0, o1;
    o0.x = round_tf32(v0.x); o0.y = round_tf32(v1.x);
    o0.z = round_tf32(v0.y); o0.w = round_tf32(v1.y);
    o1.x = round_tf32(v0.z); o1.y = round_tf32(v1.z);
    o1.z = round_tf32(v0.w); o1.w = round_tf32(v1.w);
    ((float4*)out)[2 * i]     = o0;
    ((float4*)out)[2 * i + 1] = o1;
}

// ---------------- transpose + round + K-permute: out[n][P(k)] = in[k][n] -------
__global__ void transpose_rp_kernel(const float* __restrict__ in,
                                    float* __restrict__ out, int R, int C)
{
    __shared__ float tb[32][33];
    int c0 = blockIdx.x * 32, r0 = blockIdx.y * 32;
    int x = threadIdx.x, y = threadIdx.y;    // 32 x 8
    #pragma unroll
    for (int i = 0; i < 32; i += 8)
        tb[y + i][x] = in[(size_t)(r0 + y + i) * C + c0 + x];
    __syncthreads();
    int kp = kperm_pos(r0 + x);
    #pragma unroll
    for (int i = 0; i < 32; i += 8)
        out[(size_t)(c0 + y + i) * R + kp] = round_tf32(tb[x][y + i]);
}

// ---------------- depthwise causal conv (D_CONV=4) + bias + SiLU ----------------
__global__ void conv_silu_kernel(const float* __restrict__ xz,
                                 const float* __restrict__ cw,
                                 const float* __restrict__ cb,
                                 float* __restrict__ xc)
{
    int idx = blockIdx.x * blockDim.x + threadIdx.x;
    if (idx >= NROWS * DINNER) return;
    int d  = idx & (DINNER - 1);
    int bl = idx >> 11;
    int l  = bl & (SEQL - 1);
    int b  = bl >> 11;

    float acc = cb[d];
    const float w0 = cw[d * 4 + 0], w1 = cw[d * 4 + 1],
                w2 = cw[d * 4 + 2], w3 = cw[d * 4 + 3];
    const float* base = xz + ((size_t)b * SEQL) * (2 * DINNER) + d;
    if (l >= 3) acc = fmaf(w0, base[(size_t)(l - 3) * (2 * DINNER)], acc);
    if (l >= 2) acc = fmaf(w1, base[(size_t)(l - 2) * (2 * DINNER)], acc);
    if (l >= 1) acc = fmaf(w2, base[(size_t)(l - 1) * (2 * DINNER)], acc);
    acc = fmaf(w3, base[(size_t)l * (2 * DINNER)], acc);

    float sig = 1.f / (1.f + __expf(-acc));
    xc[idx] = acc * sig;
}

// ---------------- BC^T = (xc @ W_xproj)^T : 16 rows per block ------------------
// Writes bct[c][row] (transposed) so the scan's B/C streams are contiguous in l.
__global__ __launch_bounds__(256)
void xproj_kernel(const float* __restrict__ xc,
                  const float* __restrict__ W,   // [DINNER,32]
                  float* __restrict__ bct)       // [32][NROWS]
{
    const int r0 = blockIdx.x * 16;
    const int c  = threadIdx.x & 31;
    const int st = threadIdx.x >> 5;    // 0..7
    const float* x0 = xc + (size_t)r0 * DINNER;

    float acc[16];
    #pragma unroll
    for (int r = 0; r < 16; r++) acc[r] = 0.f;

    for (int k = st; k < DINNER; k += 8) {
        float wv = W[k * 32 + c];
        #pragma unroll
        for (int r = 0; r < 16; r++)
            acc[r] = fmaf(x0[(size_t)r * DINNER + k], wv, acc[r]);
    }

    __shared__ float red[8][16][32];
    #pragma unroll
    for (int r = 0; r < 16; r++) red[st][r][c] = acc[r];
    __syncthreads();

    for (int o = threadIdx.x; o < 512; o += 256) {
        int rr = o >> 5, cc = o & 31;
        float s = 0.f;
        #pragma unroll
        for (int i = 0; i < 8; i++) s += red[i][rr][cc];
        bct[(size_t)cc * NROWS + r0 + rr] = s;
    }
}

// ---------------- selective scan: phase-structured, fused delta+gate ------------
// 16 lanes per (b,d) channel. B/C streams contiguous (from bct) -> float4 loads.
// Output written K-PERMUTED for GEMM2.
#define UNR 8
__global__ __launch_bounds__(256)
void scan_kernel(const float* __restrict__ xc,
                 const float* __restrict__ bct,   // [32][NROWS]
                 const float* __restrict__ A_log,
                 const float* __restrict__ Dvec,
                 const float* __restrict__ xz,
                 const float* __restrict__ Wdt,   // [16, DINNER]
                 const float* __restrict__ bdt,
                 float* __restrict__ g)
{
    int gid = blockIdx.x * blockDim.x + threadIdx.x;
    int s   = gid & 15;
    int ch  = gid >> 4;
    int d   = ch & (DINNER - 1);
    int b   = ch >> 11;

    const float a     = -expf(A_log[d * DSTATE + s]);
    const float Dd    = Dvec[d];
    const float wdt_s = Wdt[s * DINNER + d];
    const float bdt_d = bdt[d];

    const float* xptr = xc + (size_t)b * SEQL * DINNER + d;
    const float* zptr = xz + (size_t)b * SEQL * (2 * DINNER) + DINNER + d;
    const float* Bp   = bct + (size_t)s * NROWS + b * SEQL;
    const float* Cp   = bct + (size_t)(16 + s) * NROWS + b * SEQL;
    float*       gptr = g  + (size_t)b * SEQL * DINNER + kperm_pos(d);

    float h = 0.f;
    for (int l0 = 0; l0 < SEQL; l0 += UNR) {
        float bxt[UNR], bzv[UNR], bB[UNR], bC[UNR];
        #pragma unroll
        for (int i = 0; i < UNR; i++) {
            bxt[i] = xptr[(size_t)(l0 + i) * DINNER];
            bzv[i] = zptr[(size_t)(l0 + i) * (2 * DINNER)];
        }
        {
            float4 v0 = *(const float4*)(Bp + l0);
            float4 v1 = *(const float4*)(Bp + l0 + 4);
            bB[0] = v0.x; bB[1] = v0.y; bB[2] = v0.z; bB[3] = v0.w;
            bB[4] = v1.x; bB[5] = v1.y; bB[6] = v1.z; bB[7] = v1.w;
            float4 w0 = *(const float4*)(Cp + l0);
            float4 w1 = *(const float4*)(Cp + l0 + 4);
            bC[0] = w0.x; bC[1] = w0.y; bC[2] = w0.z; bC[3] = w0.w;
            bC[4] = w1.x; bC[5] = w1.y; bC[6] = w1.z; bC[7] = w1.w;
        }
        // phase A: deltas + decay factors (independent across i -> ILP)
        float dA[UNR], w[UNR];
        #pragma unroll
        for (int i = 0; i < UNR; i++) {
            float pd = bB[i] * wdt_s;
            pd += __shfl_xor_sync(0xffffffffu, pd, 1);
            pd += __shfl_xor_sync(0xffffffffu, pd, 2);
            pd += __shfl_xor_sync(0xffffffffu, pd, 4);
            pd += __shfl_xor_sync(0xffffffffu, pd, 8);
            float dl  = pd + bdt_d;
            float dtv = (dl > 20.f) ? dl : __logf(1.f + __expf(dl));
            dA[i] = __expf(dtv * a);
            w[i]  = dtv * bxt[i] * bB[i];
        }
        // phase B: the only true recurrence — pure FMA chain
        float p[UNR];
        #pragma unroll
        for (int i = 0; i < UNR; i++) {
            h = fmaf(dA[i], h, w[i]);
            p[i] = h * bC[i];
        }
        // phase C: output reductions (independent across i -> ILP)
        #pragma unroll
        for (int i = 0; i < UNR; i++) {
            p[i] += __shfl_xor_sync(0xffffffffu, p[i], 8);
            p[i] += __shfl_xor_sync(0xffffffffu, p[i], 4);
            p[i] += __shfl_xor_sync(0xffffffffu, p[i], 2);
            p[i] += __shfl_xor_sync(0xffffffffu, p[i], 1);
        }
        if (s == 0) {
            #pragma unroll
            for (int i = 0; i < UNR; i++) {
                float y   = fmaf(Dd, bxt[i], p[i]);
                float z   = bzv[i];
                float sig = 1.f / (1.f + __expf(-z));
                gptr[(size_t)(l0 + i) * DINNER] = round_tf32(y * (z * sig));
            }
        }
    }
}

// ---------------- launch ----------------
extern "C" void kernel_launch(void* const* d_in, const int* in_sizes, int n_in,
                              void* d_out, int out_size)
{
    const float* x      = (const float*)d_in[0];
    const float* W_in   = (const float*)d_in[1];
    const float* conv_w = (const float*)d_in[2];
    const float* conv_b = (const float*)d_in[3];
    const float* W_xprj = (const float*)d_in[4];
    const float* W_dt   = (const float*)d_in[5];
    const float* b_dt   = (const float*)d_in[6];
    const float* A_log  = (const float*)d_in[7];
    const float* Dvec   = (const float*)d_in[8];
    const float* W_out  = (const float*)d_in[9];
    float* out = (float*)d_out;

    float *xz, *xc, *bct, *gg, *xr, *wt_in, *wt_out;
    cudaGetSymbolAddress((void**)&xz, g_xz);
    cudaGetSymbolAddress((void**)&xc, g_xc);
    cudaGetSymbolAddress((void**)&bct, g_bct);
    cudaGetSymbolAddress((void**)&gg, g_gg);
    cudaGetSymbolAddress((void**)&xr, g_xr);
    cudaGetSymbolAddress((void**)&wt_in, g_wt_in);
    cudaGetSymbolAddress((void**)&wt_out, g_wt_out);

    // 0) preprocess operands: round to tf32, transpose weights to [N,K], permute K
    {
        int n8 = (NROWS * DMODEL) / 8;
        round_perm_kernel<<<(n8 + 255) / 256, 256>>>(x, xr, n8);
        dim3 blk(32, 8);
        transpose_rp_kernel<<<dim3((2 * DINNER) / 32, DMODEL / 32), blk>>>(W_in, wt_in, DMODEL, 2 * DINNER);
        transpose_rp_kernel<<<dim3(DMODEL / 32, DINNER / 32), blk>>>(W_out, wt_out, DINNER, DMODEL);
    }
    // 1) xz = x @ W_in   (M=4096, N=4096, K=1024), 128-row tiles
    {
        dim3 grid((2 * DINNER) / 128, NROWS / 128);
        tf32gemm_kernel<128><<<grid, 128>>>(xr, wt_in, xz, NROWS, 2 * DINNER, DMODEL);
    }
    // 2) conv + SiLU
    {
        int total = NROWS * DINNER;
        conv_silu_kernel<<<(total + 255) / 256, 256>>>(xz, conv_w, conv_b, xc);
    }
    // 3) BC^T = (xc @ W_xproj)^T
    xproj_kernel<<<NROWS / 16, 256>>>(xc, W_xprj, bct);
    // 4) scan (delta fused, +D, +gate, tf32 + K-permuted output)
    {
        int total = BATCH * DINNER * DSTATE;   // 65536
        scan_kernel<<<total / 256, 256>>>(xc, bct, A_log, Dvec, xz, W_dt, b_dt, gg);
    }
    // 5) out = g @ W_out  (M=4096, N=1024, K=2048), 64-row tiles for 512 CTAs
    {
        dim3 grid(DMODEL / 128, NROWS / 64);
        tf32gemm_kernel<64><<<grid, 128>>>(gg, wt_out, out, NROWS, DMODEL, DINNER);
    }
}

// round 9
// speedup vs baseline: 1.1043x; 1.1043x over previous
#include <cuda_runtime.h>
#include <cuda_bf16.h>
#include <math.h>
#include <stdint.h>

// ---------------- problem constants ----------------
#define BATCH   2
#define SEQL    2048
#define DMODEL  1024
#define DSTATE  16
#define DINNER  2048
#define NROWS   (BATCH * SEQL)   // 4096

// ---------------- scratch (static device globals; no allocation) ----------------
__device__ float g_xz[NROWS * 2 * DINNER];     // (xa | z)
__device__ float g_xc[NROWS * DINNER];         // conv+silu
__device__ float g_bc[NROWS * 32];             // [B_ssm(16) | C_ssm(16)] per row
__device__ float g_dt[NROWS * DINNER];         // delta (softplus)
__device__ float g_gg[NROWS * DINNER];         // scan output, tf32, K-PERMUTED
__device__ float g_xr[NROWS * DMODEL];         // x, tf32, K-PERMUTED
__device__ float g_wt_in[2 * DINNER * DMODEL]; // W_in^T [4096][1024], tf32, K-perm
__device__ float g_wt_out[DMODEL * DINNER];    // W_out^T [1024][2048], tf32, K-perm

// ---------------- helpers ----------------
__device__ __forceinline__ void cpasync16(void* dst, const void* src) {
    uint32_t d = (uint32_t)__cvta_generic_to_shared(dst);
    asm volatile("cp.async.cg.shared.global [%0], [%1], 16;\n" :: "r"(d), "l"(src));
}
#define CP_COMMIT() asm volatile("cp.async.commit_group;\n" ::: "memory")
#define CP_WAIT0()  asm volatile("cp.async.wait_group 0;\n" ::: "memory")

__device__ __forceinline__ float round_tf32(float x) {
    uint32_t r;
    asm("cvt.rna.tf32.f32 %0, %1;" : "=r"(r) : "f"(x));
    return __uint_as_float(r);
}
// position of original k inside the permuted 8-group: 0,4,1,5,2,6,3,7
__device__ __forceinline__ int kperm_pos(int k) {
    return (k & ~7) | ((k & 4) ? (((k & 3) << 1) | 1) : ((k & 3) << 1));
}

// =======================================================================
// TF32 mma.sync GEMM, K-PERMUTED operands, B pre-transposed to [N,K].
// C[M,N] = A[M,K] @ B^T.  CTA tile TM x 128 x 16, 128 thr = 4 warps (2x2).
// Fragment loads are LDS.64. Safe pipeline: wait -> sync -> issue-next
// -> compute (measured neutral vs racy version; GEMM1 228us).
// =======================================================================
#define SSTR 24

template<int TM>
__global__ __launch_bounds__(128)
void tf32gemm_kernel(const float* __restrict__ A, const float* __restrict__ Bt,
                     float* __restrict__ C, int M, int N, int K)
{
    constexpr int WM = TM / 2;
    constexpr int MT = TM / 32;

    __shared__ float As[2][TM][SSTR];
    __shared__ float Bs[2][128][SSTR];

    const int tid  = threadIdx.x;
    const int warp = tid >> 5;
    const int lane = tid & 31;
    const int wm   = warp >> 1;
    const int wn   = warp & 1;
    const int g    = lane >> 2;
    const int t    = lane & 3;

    const int m0 = blockIdx.y * TM;
    const int n0 = blockIdx.x * 128;

    float acc[MT][8][4];
    #pragma unroll
    for (int i = 0; i < MT; i++)
        #pragma unroll
        for (int j = 0; j < 8; j++)
            #pragma unroll
            for (int v = 0; v < 4; v++) acc[i][j][v] = 0.f;

    #define LOAD_CHUNK(kt, st) do {                                            \
        _Pragma("unroll")                                                      \
        for (int it = 0; it < TM / 32; it++) {                                 \
            int id = it * 128 + tid;                                           \
            int row = id >> 2, seg = (id & 3) * 4;                             \
            cpasync16(&As[st][row][seg],                                       \
                      A + (size_t)(m0 + row) * K + (kt) * 16 + seg);           \
        }                                                                      \
        _Pragma("unroll")                                                      \
        for (int it = 0; it < 4; it++) {                                       \
            int id = it * 128 + tid;                                           \
            int row = id >> 2, seg = (id & 3) * 4;                             \
            cpasync16(&Bs[st][row][seg],                                       \
                      Bt + (size_t)(n0 + row) * K + (kt) * 16 + seg);          \
        }                                                                      \
        CP_COMMIT();                                                           \
    } while (0)

    const int nk = K / 16;

    LOAD_CHUNK(0, 0);

    for (int kt = 0; kt < nk; kt++) {
        const int cur = kt & 1;
        CP_WAIT0();
        __syncthreads();
        if (kt + 1 < nk)
            LOAD_CHUNK(kt + 1, cur ^ 1);

        #pragma unroll
        for (int kk = 0; kk < 16; kk += 8) {
            float2 av0[MT], av1[MT], bv[8];
            #pragma unroll
            for (int mt = 0; mt < MT; mt++) {
                const int mr = wm * WM + mt * 16 + g;
                av0[mt] = *(const float2*)&As[cur][mr][kk + 2 * t];
                av1[mt] = *(const float2*)&As[cur][mr + 8][kk + 2 * t];
            }
            #pragma unroll
            for (int nt = 0; nt < 8; nt++) {
                const int nr = wn * 64 + nt * 8 + g;
                bv[nt] = *(const float2*)&Bs[cur][nr][kk + 2 * t];
            }
            #pragma unroll
            for (int mt = 0; mt < MT; mt++)
                #pragma unroll
                for (int nt = 0; nt < 8; nt++) {
                    float* c = acc[mt][nt];
                    asm volatile(
                        "mma.sync.aligned.m16n8k8.row.col.f32.tf32.tf32.f32 "
                        "{%0,%1,%2,%3}, {%4,%5,%6,%7}, {%8,%9}, {%0,%1,%2,%3};\n"
                        : "+f"(c[0]), "+f"(c[1]), "+f"(c[2]), "+f"(c[3])
                        : "r"(__float_as_uint(av0[mt].x)), "r"(__float_as_uint(av1[mt].x)),
                          "r"(__float_as_uint(av0[mt].y)), "r"(__float_as_uint(av1[mt].y)),
                          "r"(__float_as_uint(bv[nt].x)),  "r"(__float_as_uint(bv[nt].y)));
                }
        }
    }
    #undef LOAD_CHUNK

    #pragma unroll
    for (int mt = 0; mt < MT; mt++) {
        #pragma unroll
        for (int nt = 0; nt < 8; nt++) {
            const size_t row = (size_t)m0 + wm * WM + mt * 16 + g;
            const int    col = n0 + wn * 64 + nt * 8 + 2 * t;
            *(float2*)(C + row * N + col)       = make_float2(acc[mt][nt][0], acc[mt][nt][1]);
            *(float2*)(C + (row + 8) * N + col) = make_float2(acc[mt][nt][2], acc[mt][nt][3]);
        }
    }
}

// ---------------- round + K-permute (linear, rows are multiples of 8) ----------
__global__ void round_perm_kernel(const float* __restrict__ in,
                                  float* __restrict__ out, int n8)
{
    int i = blockIdx.x * blockDim.x + threadIdx.x;
    if (i >= n8) return;
    float4 v0 = ((const float4*)in)[2 * i];
    float4 v1 = ((const float4*)in)[2 * i + 1];
    float4 o0, o1;
    o0.x = round_tf32(v0.x); o0.y = round_tf32(v1.x);
    o0.z = round_tf32(v0.y); o0.w = round_tf32(v1.y);
    o1.x = round_tf32(v0.z); o1.y = round_tf32(v1.z);
    o1.z = round_tf32(v0.w); o1.w = round_tf32(v1.w);
    ((float4*)out)[2 * i]     = o0;
    ((float4*)out)[2 * i + 1] = o1;
}

// ---------------- transpose + round + K-permute: out[n][P(k)] = in[k][n] -------
__global__ void transpose_rp_kernel(const float* __restrict__ in,
                                    float* __restrict__ out, int R, int C)
{
    __shared__ float tb[32][33];
    int c0 = blockIdx.x * 32, r0 = blockIdx.y * 32;
    int x = threadIdx.x, y = threadIdx.y;    // 32 x 8
    #pragma unroll
    for (int i = 0; i < 32; i += 8)
        tb[y + i][x] = in[(size_t)(r0 + y + i) * C + c0 + x];
    __syncthreads();
    int kp = kperm_pos(r0 + x);
    #pragma unroll
    for (int i = 0; i < 32; i += 8)
        out[(size_t)(c0 + y + i) * R + kp] = round_tf32(tb[x][y + i]);
}

// ---------------- depthwise causal conv (D_CONV=4) + bias + SiLU ----------------
__global__ void conv_silu_kernel(const float* __restrict__ xz,
                                 const float* __restrict__ cw,
                                 const float* __restrict__ cb,
                                 float* __restrict__ xc)
{
    int idx = blockIdx.x * blockDim.x + threadIdx.x;
    if (idx >= NROWS * DINNER) return;
    int d  = idx & (DINNER - 1);
    int bl = idx >> 11;
    int l  = bl & (SEQL - 1);
    int b  = bl >> 11;

    float acc = cb[d];
    const float w0 = cw[d * 4 + 0], w1 = cw[d * 4 + 1],
                w2 = cw[d * 4 + 2], w3 = cw[d * 4 + 3];
    const float* base = xz + ((size_t)b * SEQL) * (2 * DINNER) + d;
    if (l >= 3) acc = fmaf(w0, base[(size_t)(l - 3) * (2 * DINNER)], acc);
    if (l >= 2) acc = fmaf(w1, base[(size_t)(l - 2) * (2 * DINNER)], acc);
    if (l >= 1) acc = fmaf(w2, base[(size_t)(l - 1) * (2 * DINNER)], acc);
    acc = fmaf(w3, base[(size_t)l * (2 * DINNER)], acc);

    float sig = 1.f / (1.f + __expf(-acc));
    xc[idx] = acc * sig;
}

// ---------------- BC = xc @ W_xproj : 4 rows per block (R7 layout) -------------
__global__ void xproj_kernel(const float* __restrict__ xc,
                             const float* __restrict__ W,   // [DINNER,32]
                             float* __restrict__ bc)        // [NROWS][32]
{
    const int r0 = blockIdx.x * 4;
    const int c  = threadIdx.x & 31;
    const int st = threadIdx.x >> 5;
    const float* x0 = xc + (size_t)r0 * DINNER;

    float a0 = 0.f, a1 = 0.f, a2 = 0.f, a3 = 0.f;
    for (int k = st; k < DINNER; k += 8) {
        float wv = W[k * 32 + c];
        a0 = fmaf(x0[k],              wv, a0);
        a1 = fmaf(x0[DINNER + k],     wv, a1);
        a2 = fmaf(x0[2 * DINNER + k], wv, a2);
        a3 = fmaf(x0[3 * DINNER + k], wv, a3);
    }

    __shared__ float red[8][4][32];
    red[st][0][c] = a0; red[st][1][c] = a1;
    red[st][2][c] = a2; red[st][3][c] = a3;
    __syncthreads();
    if (threadIdx.x < 128) {
        int rc = threadIdx.x & 31;
        int rr = threadIdx.x >> 5;
        float s = 0.f;
        #pragma unroll
        for (int i = 0; i < 8; i++) s += red[i][rr][rc];
        bc[(size_t)(r0 + rr) * 32 + rc] = s;
    }
}

// ---------------- delta = softplus(B_ssm @ W_dt + b_dt) : standalone (45us) ----
__global__ void delta_kernel(const float* __restrict__ bc,
                             const float* __restrict__ Wdt,   // [16,DINNER]
                             const float* __restrict__ bdt,
                             float* __restrict__ dt)
{
    int idx = blockIdx.x * blockDim.x + threadIdx.x;
    if (idx >= NROWS * DINNER) return;
    int d = idx & (DINNER - 1);
    int r = idx >> 11;
    const float* Br = bc + (size_t)r * 32;
    float acc = bdt[d];
    #pragma unroll
    for (int s = 0; s < DSTATE; s++)
        acc = fmaf(Br[s], Wdt[s * DINNER + d], acc);
    float sp = (acc > 20.f) ? acc : __logf(1.f + __expf(acc));
    dt[idx] = sp;
}

// ---------------- selective scan: slim (no delta butterflies), prefetch-8 -------
// 16 lanes per (b,d). Per step: 1 exp + fma chain + 4 output shuffles.
// Output written K-PERMUTED for GEMM2.
#define UNR 8
__global__ __launch_bounds__(256)
void scan_kernel(const float* __restrict__ xc,
                 const float* __restrict__ bc,     // [NROWS][32]
                 const float* __restrict__ dt,     // [NROWS][DINNER]
                 const float* __restrict__ A_log,
                 const float* __restrict__ Dvec,
                 const float* __restrict__ xz,
                 float* __restrict__ g)
{
    int gid = blockIdx.x * blockDim.x + threadIdx.x;
    int s   = gid & 15;
    int ch  = gid >> 4;
    int d   = ch & (DINNER - 1);
    int b   = ch >> 11;

    const float a  = -expf(A_log[d * DSTATE + s]);
    const float Dd = Dvec[d];

    const float* xptr = xc + (size_t)b * SEQL * DINNER + d;
    const float* dptr = dt + (size_t)b * SEQL * DINNER + d;
    const float* zptr = xz + (size_t)b * SEQL * (2 * DINNER) + DINNER + d;
    const float* bcb  = bc + (size_t)b * SEQL * 32;
    float*       gptr = g  + (size_t)b * SEQL * DINNER + kperm_pos(d);

    float h = 0.f;
    for (int l0 = 0; l0 < SEQL; l0 += UNR) {
        float bxt[UNR], bzv[UNR], bdt_[UNR], bB[UNR], bC[UNR];
        #pragma unroll
        for (int i = 0; i < UNR; i++) {
            bxt[i]  = xptr[(size_t)(l0 + i) * DINNER];
            bdt_[i] = dptr[(size_t)(l0 + i) * DINNER];
            bzv[i]  = zptr[(size_t)(l0 + i) * (2 * DINNER)];
            bB[i]   = bcb[(l0 + i) * 32 + s];
            bC[i]   = bcb[(l0 + i) * 32 + 16 + s];
        }
        // phase A: decay factors + inputs (independent -> ILP)
        float dA[UNR], w[UNR];
        #pragma unroll
        for (int i = 0; i < UNR; i++) {
            dA[i] = __expf(bdt_[i] * a);
            w[i]  = bdt_[i] * bxt[i] * bB[i];
        }
        // phase B: the only true recurrence — pure FMA chain
        float p[UNR];
        #pragma unroll
        for (int i = 0; i < UNR; i++) {
            h = fmaf(dA[i], h, w[i]);
            p[i] = h * bC[i];
        }
        // phase C: output reductions (independent -> ILP)
        #pragma unroll
        for (int i = 0; i < UNR; i++) {
            p[i] += __shfl_xor_sync(0xffffffffu, p[i], 8);
            p[i] += __shfl_xor_sync(0xffffffffu, p[i], 4);
            p[i] += __shfl_xor_sync(0xffffffffu, p[i], 2);
            p[i] += __shfl_xor_sync(0xffffffffu, p[i], 1);
        }
        if (s == 0) {
            #pragma unroll
            for (int i = 0; i < UNR; i++) {
                float y   = fmaf(Dd, bxt[i], p[i]);
                float z   = bzv[i];
                float sig = 1.f / (1.f + __expf(-z));
                gptr[(size_t)(l0 + i) * DINNER] = round_tf32(y * (z * sig));
            }
        }
    }
}

// ---------------- launch ----------------
extern "C" void kernel_launch(void* const* d_in, const int* in_sizes, int n_in,
                              void* d_out, int out_size)
{
    const float* x      = (const float*)d_in[0];
    const float* W_in   = (const float*)d_in[1];
    const float* conv_w = (const float*)d_in[2];
    const float* conv_b = (const float*)d_in[3];
    const float* W_xprj = (const float*)d_in[4];
    const float* W_dt   = (const float*)d_in[5];
    const float* b_dt   = (const float*)d_in[6];
    const float* A_log  = (const float*)d_in[7];
    const float* Dvec   = (const float*)d_in[8];
    const float* W_out  = (const float*)d_in[9];
    float* out = (float*)d_out;

    float *xz, *xc, *bc, *dt, *gg, *xr, *wt_in, *wt_out;
    cudaGetSymbolAddress((void**)&xz, g_xz);
    cudaGetSymbolAddress((void**)&xc, g_xc);
    cudaGetSymbolAddress((void**)&bc, g_bc);
    cudaGetSymbolAddress((void**)&dt, g_dt);
    cudaGetSymbolAddress((void**)&gg, g_gg);
    cudaGetSymbolAddress((void**)&xr, g_xr);
    cudaGetSymbolAddress((void**)&wt_in, g_wt_in);
    cudaGetSymbolAddress((void**)&wt_out, g_wt_out);

    // 0) preprocess operands: round to tf32, transpose weights to [N,K], permute K
    {
        int n8 = (NROWS * DMODEL) / 8;
        round_perm_kernel<<<(n8 + 255) / 256, 256>>>(x, xr, n8);
        dim3 blk(32, 8);
        transpose_rp_kernel<<<dim3((2 * DINNER) / 32, DMODEL / 32), blk>>>(W_in, wt_in, DMODEL, 2 * DINNER);
        transpose_rp_kernel<<<dim3(DMODEL / 32, DINNER / 32), blk>>>(W_out, wt_out, DINNER, DMODEL);
    }
    // 1) xz = x @ W_in   (M=4096, N=4096, K=1024), 128-row tiles
    {
        dim3 grid((2 * DINNER) / 128, NROWS / 128);
        tf32gemm_kernel<128><<<grid, 128>>>(xr, wt_in, xz, NROWS, 2 * DINNER, DMODEL);
    }
    // 2) conv + SiLU
    {
        int total = NROWS * DINNER;
        conv_silu_kernel<<<(total + 255) / 256, 256>>>(xz, conv_w, conv_b, xc);
    }
    // 3) BC = xc @ W_xproj
    xproj_kernel<<<NROWS / 4, 256>>>(xc, W_xprj, bc);
    // 4) delta = softplus(B @ W_dt + b_dt)
    {
        int total = NROWS * DINNER;
        delta_kernel<<<(total + 255) / 256, 256>>>(bc, W_dt, b_dt, dt);
    }
    // 5) scan (+D, +gate, tf32 + K-permuted output)
    {
        int total = BATCH * DINNER * DSTATE;   // 65536
        scan_kernel<<<total / 256, 256>>>(xc, bc, dt, A_log, Dvec, xz, gg);
    }
    // 6) out = g @ W_out  (M=4096, N=1024, K=2048), 64-row tiles for 512 CTAs
    {
        dim3 grid(DMODEL / 128, NROWS / 64);
        tf32gemm_kernel<64><<<grid, 128>>>(gg, wt_out, out, NROWS, DMODEL, DINNER);
    }
}

// round 10
// speedup vs baseline: 1.2280x; 1.1120x over previous
#include <cuda_runtime.h>
#include <cuda_bf16.h>
#include <math.h>
#include <stdint.h>

// ---------------- problem constants ----------------
#define BATCH   2
#define SEQL    2048
#define DMODEL  1024
#define DSTATE  16
#define DINNER  2048
#define NROWS   (BATCH * SEQL)   // 4096

// ---------------- scratch (static device globals; no allocation) ----------------
__device__ float g_xz[NROWS * 2 * DINNER];     // (xa | z)
__device__ float g_xc[NROWS * DINNER];         // conv+silu
__device__ float g_bc[NROWS * 32];             // [B_ssm(16) | C_ssm(16)] per row
__device__ float g_gg[NROWS * DINNER];         // scan output, tf32, K-PERMUTED
__device__ float g_xr[NROWS * DMODEL];         // x, tf32, K-PERMUTED
__device__ float g_wt_in[2 * DINNER * DMODEL]; // W_in^T [4096][1024], tf32, K-perm
__device__ float g_wt_out[DMODEL * DINNER];    // W_out^T [1024][2048], tf32, K-perm

// ---------------- helpers ----------------
__device__ __forceinline__ void cpasync16(void* dst, const void* src) {
    uint32_t d = (uint32_t)__cvta_generic_to_shared(dst);
    asm volatile("cp.async.cg.shared.global [%0], [%1], 16;\n" :: "r"(d), "l"(src));
}
#define CP_COMMIT() asm volatile("cp.async.commit_group;\n" ::: "memory")
#define CP_WAIT0()  asm volatile("cp.async.wait_group 0;\n" ::: "memory")

__device__ __forceinline__ float round_tf32(float x) {
    uint32_t r;
    asm("cvt.rna.tf32.f32 %0, %1;" : "=r"(r) : "f"(x));
    return __uint_as_float(r);
}
// position of original k inside the permuted 8-group: 0,4,1,5,2,6,3,7
__device__ __forceinline__ int kperm_pos(int k) {
    return (k & ~7) | ((k & 4) ? (((k & 3) << 1) | 1) : ((k & 3) << 1));
}

// =======================================================================
// TF32 mma.sync GEMM (measured stable: GEMM1 = 228us, tensor 56%).
// K-PERMUTED operands, B pre-transposed to [N,K]. CTA TM x 128 x 16,
// 128 thr = 4 warps (2x2). Fragment loads are LDS.64. Safe pipeline.
// =======================================================================
#define SSTR 24

template<int TM>
__global__ __launch_bounds__(128)
void tf32gemm_kernel(const float* __restrict__ A, const float* __restrict__ Bt,
                     float* __restrict__ C, int M, int N, int K)
{
    constexpr int WM = TM / 2;
    constexpr int MT = TM / 32;

    __shared__ float As[2][TM][SSTR];
    __shared__ float Bs[2][128][SSTR];

    const int tid  = threadIdx.x;
    const int warp = tid >> 5;
    const int lane = tid & 31;
    const int wm   = warp >> 1;
    const int wn   = warp & 1;
    const int g    = lane >> 2;
    const int t    = lane & 3;

    const int m0 = blockIdx.y * TM;
    const int n0 = blockIdx.x * 128;

    float acc[MT][8][4];
    #pragma unroll
    for (int i = 0; i < MT; i++)
        #pragma unroll
        for (int j = 0; j < 8; j++)
            #pragma unroll
            for (int v = 0; v < 4; v++) acc[i][j][v] = 0.f;

    #define LOAD_CHUNK(kt, st) do {                                            \
        _Pragma("unroll")                                                      \
        for (int it = 0; it < TM / 32; it++) {                                 \
            int id = it * 128 + tid;                                           \
            int row = id >> 2, seg = (id & 3) * 4;                             \
            cpasync16(&As[st][row][seg],                                       \
                      A + (size_t)(m0 + row) * K + (kt) * 16 + seg);           \
        }                                                                      \
        _Pragma("unroll")                                                      \
        for (int it = 0; it < 4; it++) {                                       \
            int id = it * 128 + tid;                                           \
            int row = id >> 2, seg = (id & 3) * 4;                             \
            cpasync16(&Bs[st][row][seg],                                       \
                      Bt + (size_t)(n0 + row) * K + (kt) * 16 + seg);          \
        }                                                                      \
        CP_COMMIT();                                                           \
    } while (0)

    const int nk = K / 16;

    LOAD_CHUNK(0, 0);

    for (int kt = 0; kt < nk; kt++) {
        const int cur = kt & 1;
        CP_WAIT0();
        __syncthreads();
        if (kt + 1 < nk)
            LOAD_CHUNK(kt + 1, cur ^ 1);

        #pragma unroll
        for (int kk = 0; kk < 16; kk += 8) {
            float2 av0[MT], av1[MT], bv[8];
            #pragma unroll
            for (int mt = 0; mt < MT; mt++) {
                const int mr = wm * WM + mt * 16 + g;
                av0[mt] = *(const float2*)&As[cur][mr][kk + 2 * t];
                av1[mt] = *(const float2*)&As[cur][mr + 8][kk + 2 * t];
            }
            #pragma unroll
            for (int nt = 0; nt < 8; nt++) {
                const int nr = wn * 64 + nt * 8 + g;
                bv[nt] = *(const float2*)&Bs[cur][nr][kk + 2 * t];
            }
            #pragma unroll
            for (int mt = 0; mt < MT; mt++)
                #pragma unroll
                for (int nt = 0; nt < 8; nt++) {
                    float* c = acc[mt][nt];
                    asm volatile(
                        "mma.sync.aligned.m16n8k8.row.col.f32.tf32.tf32.f32 "
                        "{%0,%1,%2,%3}, {%4,%5,%6,%7}, {%8,%9}, {%0,%1,%2,%3};\n"
                        : "+f"(c[0]), "+f"(c[1]), "+f"(c[2]), "+f"(c[3])
                        : "r"(__float_as_uint(av0[mt].x)), "r"(__float_as_uint(av1[mt].x)),
                          "r"(__float_as_uint(av0[mt].y)), "r"(__float_as_uint(av1[mt].y)),
                          "r"(__float_as_uint(bv[nt].x)),  "r"(__float_as_uint(bv[nt].y)));
                }
        }
    }
    #undef LOAD_CHUNK

    #pragma unroll
    for (int mt = 0; mt < MT; mt++) {
        #pragma unroll
        for (int nt = 0; nt < 8; nt++) {
            const size_t row = (size_t)m0 + wm * WM + mt * 16 + g;
            const int    col = n0 + wn * 64 + nt * 8 + 2 * t;
            *(float2*)(C + row * N + col)       = make_float2(acc[mt][nt][0], acc[mt][nt][1]);
            *(float2*)(C + (row + 8) * N + col) = make_float2(acc[mt][nt][2], acc[mt][nt][3]);
        }
    }
}

// ---------------- round + K-permute (linear, rows are multiples of 8) ----------
__global__ void round_perm_kernel(const float* __restrict__ in,
                                  float* __restrict__ out, int n8)
{
    int i = blockIdx.x * blockDim.x + threadIdx.x;
    if (i >= n8) return;
    float4 v0 = ((const float4*)in)[2 * i];
    float4 v1 = ((const float4*)in)[2 * i + 1];
    float4 o0, o1;
    o0.x = round_tf32(v0.x); o0.y = round_tf32(v1.x);
    o0.z = round_tf32(v0.y); o0.w = round_tf32(v1.y);
    o1.x = round_tf32(v0.z); o1.y = round_tf32(v1.z);
    o1.z = round_tf32(v0.w); o1.w = round_tf32(v1.w);
    ((float4*)out)[2 * i]     = o0;
    ((float4*)out)[2 * i + 1] = o1;
}

// ---------------- transpose + round + K-permute: out[n][P(k)] = in[k][n] -------
__global__ void transpose_rp_kernel(const float* __restrict__ in,
                                    float* __restrict__ out, int R, int C)
{
    __shared__ float tb[32][33];
    int c0 = blockIdx.x * 32, r0 = blockIdx.y * 32;
    int x = threadIdx.x, y = threadIdx.y;    // 32 x 8
    #pragma unroll
    for (int i = 0; i < 32; i += 8)
        tb[y + i][x] = in[(size_t)(r0 + y + i) * C + c0 + x];
    __syncthreads();
    int kp = kperm_pos(r0 + x);
    #pragma unroll
    for (int i = 0; i < 32; i += 8)
        out[(size_t)(c0 + y + i) * R + kp] = round_tf32(tb[x][y + i]);
}

// ---------------- depthwise causal conv (D_CONV=4) + bias + SiLU ----------------
__global__ void conv_silu_kernel(const float* __restrict__ xz,
                                 const float* __restrict__ cw,
                                 const float* __restrict__ cb,
                                 float* __restrict__ xc)
{
    int idx = blockIdx.x * blockDim.x + threadIdx.x;
    if (idx >= NROWS * DINNER) return;
    int d  = idx & (DINNER - 1);
    int bl = idx >> 11;
    int l  = bl & (SEQL - 1);
    int b  = bl >> 11;

    float acc = cb[d];
    const float w0 = cw[d * 4 + 0], w1 = cw[d * 4 + 1],
                w2 = cw[d * 4 + 2], w3 = cw[d * 4 + 3];
    const float* base = xz + ((size_t)b * SEQL) * (2 * DINNER) + d;
    if (l >= 3) acc = fmaf(w0, base[(size_t)(l - 3) * (2 * DINNER)], acc);
    if (l >= 2) acc = fmaf(w1, base[(size_t)(l - 2) * (2 * DINNER)], acc);
    if (l >= 1) acc = fmaf(w2, base[(size_t)(l - 1) * (2 * DINNER)], acc);
    acc = fmaf(w3, base[(size_t)l * (2 * DINNER)], acc);

    float sig = 1.f / (1.f + __expf(-acc));
    xc[idx] = acc * sig;
}

// ---------------- BC = xc @ W_xproj : 4 rows per block (R7 layout) -------------
__global__ void xproj_kernel(const float* __restrict__ xc,
                             const float* __restrict__ W,   // [DINNER,32]
                             float* __restrict__ bc)        // [NROWS][32]
{
    const int r0 = blockIdx.x * 4;
    const int c  = threadIdx.x & 31;
    const int st = threadIdx.x >> 5;
    const float* x0 = xc + (size_t)r0 * DINNER;

    float a0 = 0.f, a1 = 0.f, a2 = 0.f, a3 = 0.f;
    for (int k = st; k < DINNER; k += 8) {
        float wv = W[k * 32 + c];
        a0 = fmaf(x0[k],              wv, a0);
        a1 = fmaf(x0[DINNER + k],     wv, a1);
        a2 = fmaf(x0[2 * DINNER + k], wv, a2);
        a3 = fmaf(x0[3 * DINNER + k], wv, a3);
    }

    __shared__ float red[8][4][32];
    red[st][0][c] = a0; red[st][1][c] = a1;
    red[st][2][c] = a2; red[st][3][c] = a3;
    __syncthreads();
    if (threadIdx.x < 128) {
        int rc = threadIdx.x & 31;
        int rr = threadIdx.x >> 5;
        float s = 0.f;
        #pragma unroll
        for (int i = 0; i < 8; i++) s += red[i][rr][rc];
        bc[(size_t)(r0 + rr) * 32 + rc] = s;
    }
}

// ---------------- selective scan: 8 lanes x 2 states per (b,d) channel ----------
// Lane j owns states 2j, 2j+1 (B/C/Wdt/A_log pairs load as float2).
// delta fused: softplus(sum_s B*Wdt + b_dt) via pairwise + 3-deep butterfly.
// Each warp covers 4 channels (was 2) -> ~half the warp-instructions per step.
// Output written K-PERMUTED for GEMM2.
#define UNR 8
__global__ __launch_bounds__(256)
void scan_kernel(const float* __restrict__ xc,
                 const float* __restrict__ bc,     // [NROWS][32]
                 const float* __restrict__ A_log,  // [DINNER][16]
                 const float* __restrict__ Dvec,
                 const float* __restrict__ xz,
                 const float* __restrict__ Wdt,    // [16, DINNER]
                 const float* __restrict__ bdt,
                 float* __restrict__ g)
{
    int gid = blockIdx.x * blockDim.x + threadIdx.x;   // BATCH*DINNER*8
    int j   = gid & 7;                  // lane in 8-group
    int ch  = gid >> 3;
    int d   = ch & (DINNER - 1);
    int b   = ch >> 11;
    int s0  = 2 * j;

    float2 al = *(const float2*)&A_log[d * DSTATE + s0];
    const float a0 = -expf(al.x);
    const float a1 = -expf(al.y);
    const float Dd    = Dvec[d];
    const float wdt0  = Wdt[s0 * DINNER + d];
    const float wdt1  = Wdt[(s0 + 1) * DINNER + d];
    const float bdt_d = bdt[d];

    const float* xptr = xc + (size_t)b * SEQL * DINNER + d;
    const float* zptr = xz + (size_t)b * SEQL * (2 * DINNER) + DINNER + d;
    const float* bcb  = bc + (size_t)b * SEQL * 32;
    float*       gptr = g  + (size_t)b * SEQL * DINNER + kperm_pos(d);

    float h0 = 0.f, h1 = 0.f;
    for (int l0 = 0; l0 < SEQL; l0 += UNR) {
        float  bxt[UNR], bzv[UNR];
        float2 bB[UNR], bC[UNR];
        #pragma unroll
        for (int i = 0; i < UNR; i++) {
            bxt[i] = xptr[(size_t)(l0 + i) * DINNER];
            bzv[i] = zptr[(size_t)(l0 + i) * (2 * DINNER)];
            bB[i]  = *(const float2*)&bcb[(l0 + i) * 32 + s0];
            bC[i]  = *(const float2*)&bcb[(l0 + i) * 32 + 16 + s0];
        }
        // phase A: deltas + decay factors (independent across i -> ILP)
        float dA0[UNR], dA1[UNR], w0[UNR], w1[UNR];
        #pragma unroll
        for (int i = 0; i < UNR; i++) {
            float pd = fmaf(bB[i].x, wdt0, bB[i].y * wdt1);
            pd += __shfl_xor_sync(0xffffffffu, pd, 1);
            pd += __shfl_xor_sync(0xffffffffu, pd, 2);
            pd += __shfl_xor_sync(0xffffffffu, pd, 4);
            float dl  = pd + bdt_d;
            float dtv = (dl > 20.f) ? dl : __logf(1.f + __expf(dl));
            dA0[i] = __expf(dtv * a0);
            dA1[i] = __expf(dtv * a1);
            float dx = dtv * bxt[i];
            w0[i] = dx * bB[i].x;
            w1[i] = dx * bB[i].y;
        }
        // phase B: the recurrences — two interleaved FMA chains
        float p[UNR];
        #pragma unroll
        for (int i = 0; i < UNR; i++) {
            h0 = fmaf(dA0[i], h0, w0[i]);
            h1 = fmaf(dA1[i], h1, w1[i]);
            p[i] = fmaf(h0, bC[i].x, h1 * bC[i].y);
        }
        // phase C: output reductions (independent -> ILP)
        #pragma unroll
        for (int i = 0; i < UNR; i++) {
            p[i] += __shfl_xor_sync(0xffffffffu, p[i], 4);
            p[i] += __shfl_xor_sync(0xffffffffu, p[i], 2);
            p[i] += __shfl_xor_sync(0xffffffffu, p[i], 1);
        }
        if (j == 0) {
            #pragma unroll
            for (int i = 0; i < UNR; i++) {
                float y   = fmaf(Dd, bxt[i], p[i]);
                float z   = bzv[i];
                float sig = 1.f / (1.f + __expf(-z));
                gptr[(size_t)(l0 + i) * DINNER] = round_tf32(y * (z * sig));
            }
        }
    }
}

// ---------------- launch ----------------
extern "C" void kernel_launch(void* const* d_in, const int* in_sizes, int n_in,
                              void* d_out, int out_size)
{
    const float* x      = (const float*)d_in[0];
    const float* W_in   = (const float*)d_in[1];
    const float* conv_w = (const float*)d_in[2];
    const float* conv_b = (const float*)d_in[3];
    const float* W_xprj = (const float*)d_in[4];
    const float* W_dt   = (const float*)d_in[5];
    const float* b_dt   = (const float*)d_in[6];
    const float* A_log  = (const float*)d_in[7];
    const float* Dvec   = (const float*)d_in[8];
    const float* W_out  = (const float*)d_in[9];
    float* out = (float*)d_out;

    float *xz, *xc, *bc, *gg, *xr, *wt_in, *wt_out;
    cudaGetSymbolAddress((void**)&xz, g_xz);
    cudaGetSymbolAddress((void**)&xc, g_xc);
    cudaGetSymbolAddress((void**)&bc, g_bc);
    cudaGetSymbolAddress((void**)&gg, g_gg);
    cudaGetSymbolAddress((void**)&xr, g_xr);
    cudaGetSymbolAddress((void**)&wt_in, g_wt_in);
    cudaGetSymbolAddress((void**)&wt_out, g_wt_out);

    // 0) preprocess operands: round to tf32, transpose weights to [N,K], permute K
    {
        int n8 = (NROWS * DMODEL) / 8;
        round_perm_kernel<<<(n8 + 255) / 256, 256>>>(x, xr, n8);
        dim3 blk(32, 8);
        transpose_rp_kernel<<<dim3((2 * DINNER) / 32, DMODEL / 32), blk>>>(W_in, wt_in, DMODEL, 2 * DINNER);
        transpose_rp_kernel<<<dim3(DMODEL / 32, DINNER / 32), blk>>>(W_out, wt_out, DINNER, DMODEL);
    }
    // 1) xz = x @ W_in   (M=4096, N=4096, K=1024), 128-row tiles
    {
        dim3 grid((2 * DINNER) / 128, NROWS / 128);
        tf32gemm_kernel<128><<<grid, 128>>>(xr, wt_in, xz, NROWS, 2 * DINNER, DMODEL);
    }
    // 2) conv + SiLU
    {
        int total = NROWS * DINNER;
        conv_silu_kernel<<<(total + 255) / 256, 256>>>(xz, conv_w, conv_b, xc);
    }
    // 3) BC = xc @ W_xproj
    xproj_kernel<<<NROWS / 4, 256>>>(xc, W_xprj, bc);
    // 4) scan (delta fused, +D, +gate, tf32 + K-permuted output), 8 lanes/channel
    {
        int total = BATCH * DINNER * 8;   // 32768
        scan_kernel<<<total / 256, 256>>>(xc, bc, A_log, Dvec, xz, W_dt, b_dt, gg);
    }
    // 5) out = g @ W_out  (M=4096, N=1024, K=2048), 64-row tiles for 512 CTAs
    {
        dim3 grid(DMODEL / 128, NROWS / 64);
        tf32gemm_kernel<64><<<grid, 128>>>(gg, wt_out, out, NROWS, DMODEL, DINNER);
    }
}